// round 8
// baseline (speedup 1.0000x reference)
#include <cuda_runtime.h>
#include <cuda_bf16.h>
#include <cstdint>

// Live computation (GNN branch is dead code in the reference):
//   h1 = relu(sf @ Wfc1^T + bfc1)     [N,12] -> [N,64]   (HMMA, K padded to 16)
//   h2 = relu(h1 @ Wfc2^T + bfc2)     [N,64] -> [N,64]   (HMMA, A register-chained)
//   out = h2 @ Wp^T + bp              [N,64] -> [N,1]    (register epilogue)
//
// Both layers on mma.sync.m16n8k16 bf16 2-way split (D = Ah*Bh + Al*Bh + Ah*Bl).
// This round: 2 node-tiles per block (grid 391 -> single wave at 3 CTAs/SM),
// weights staged + split + W1 B-fragments loaded ONCE per block; the tile loop
// is sync-free (smem is read-only after the single __syncthreads).

#define NN     100000
#define SF     12
#define FC     64
#define TPB    128
#define NPB    128
#define NTILES 2
#define GRID   391            // NTILES * GRID * NPB = 100096 >= NN
#define BSTR   144            // W2 smem row stride (bytes): 9x16B, conflict-free
#define WSTR   48             // W1 smem row stride (bytes): 3x16B, conflict-free

// ---- dynamic smem layout (byte offsets) ----
#define OFF_B2H  0            // 64 x 144
#define OFF_B2L  9216         // 64 x 144
#define OFF_W1H  18432        // 64 x 48
#define OFF_W1L  21504        // 64 x 48
#define OFF_B1   24576        // float[64]
#define OFF_B2   24832        // float[64]
#define OFF_WP   25088        // float[64]
#define OFF_BP   25344        // float
#define SMEM_DYN 25600

__device__ __forceinline__ uint32_t smem_u32(const void* p) {
    uint32_t a;
    asm("{ .reg .u64 t; cvta.to.shared.u64 t, %1; cvt.u32.u64 %0, t; }"
        : "=r"(a) : "l"(p));
    return a;
}
// pack: f0 -> low bf16, f1 -> high bf16
__device__ __forceinline__ uint32_t bf16x2_of(float f0, float f1) {
    uint32_t r;
    asm("cvt.rn.bf16x2.f32 %0, %1, %2;" : "=r"(r) : "f"(f1), "f"(f0));
    return r;
}
__device__ __forceinline__ void split2(float f0, float f1, uint32_t& h, uint32_t& l) {
    h = bf16x2_of(f0, f1);
    float g0 = __uint_as_float(h << 16);
    float g1 = __uint_as_float(h & 0xffff0000u);
    l = bf16x2_of(f0 - g0, f1 - g1);
}
__device__ __forceinline__ void ldsm_x4(uint32_t* r, uint32_t addr) {
    asm volatile("ldmatrix.sync.aligned.m8n8.x4.shared.b16 {%0,%1,%2,%3}, [%4];"
                 : "=r"(r[0]), "=r"(r[1]), "=r"(r[2]), "=r"(r[3]) : "r"(addr));
}
__device__ __forceinline__ void mma_bf16(float* d, const uint32_t* a, const uint32_t* b) {
    asm volatile(
        "mma.sync.aligned.m16n8k16.row.col.f32.bf16.bf16.f32 "
        "{%0,%1,%2,%3}, {%4,%5,%6,%7}, {%8,%9}, {%0,%1,%2,%3};"
        : "+f"(d[0]), "+f"(d[1]), "+f"(d[2]), "+f"(d[3])
        : "r"(a[0]), "r"(a[1]), "r"(a[2]), "r"(a[3]), "r"(b[0]), "r"(b[1]));
}

__global__ __launch_bounds__(TPB, 3)
void fused_mlp_hmma3(const float* __restrict__ sf,
                     const float* __restrict__ W1, const float* __restrict__ b1,
                     const float* __restrict__ W2, const float* __restrict__ b2,
                     const float* __restrict__ Wp, const float* __restrict__ bp,
                     float* __restrict__ out)
{
    extern __shared__ __align__(16) char base[];
    const uint32_t sb = smem_u32(base);

    const int tid  = threadIdx.x;
    const int lane = tid & 31;
    const int w    = tid >> 5;
    const int q    = lane & 3;
    const int r4   = lane >> 2;

    // ---- stage W2 -> B2h/B2l (rows = output j, 64 bf16 k-contig, stride 144) ----
    {
        const int row = tid >> 1, half = tid & 1;
        const float* src = W2 + row * FC + half * 32;
        #pragma unroll
        for (int g = 0; g < 4; g++) {
            float4 v0 = *(const float4*)(src + g * 8);
            float4 v1 = *(const float4*)(src + g * 8 + 4);
            uint32_t h0, l0, h1_, l1_, h2, l2, h3, l3;
            split2(v0.x, v0.y, h0, l0);
            split2(v0.z, v0.w, h1_, l1_);
            split2(v1.x, v1.y, h2, l2);
            split2(v1.z, v1.w, h3, l3);
            const int off = row * BSTR + half * 64 + g * 16;
            *(uint4*)(base + OFF_B2H + off) = make_uint4(h0, h1_, h2, h3);
            *(uint4*)(base + OFF_B2L + off) = make_uint4(l0, l1_, l2, l3);
        }
    }
    // ---- stage W1 -> W1h/W1l (12 bf16 + 4 zero pad per row, stride 48) ----
    if (tid < FC) {
        const float* src = W1 + tid * SF;
        float4 v0 = *(const float4*)(src);
        float4 v1 = *(const float4*)(src + 4);
        float4 v2 = *(const float4*)(src + 8);
        uint32_t h0, l0, h1_, l1_, h2, l2, h3, l3, h4, l4, h5, l5;
        split2(v0.x, v0.y, h0, l0);
        split2(v0.z, v0.w, h1_, l1_);
        split2(v1.x, v1.y, h2, l2);
        split2(v1.z, v1.w, h3, l3);
        split2(v2.x, v2.y, h4, l4);
        split2(v2.z, v2.w, h5, l5);
        const int off = tid * WSTR;
        *(uint4*)(base + OFF_W1H + off)      = make_uint4(h0, h1_, h2, h3);
        *(uint4*)(base + OFF_W1H + off + 16) = make_uint4(h4, h5, 0u, 0u);
        *(uint4*)(base + OFF_W1L + off)      = make_uint4(l0, l1_, l2, l3);
        *(uint4*)(base + OFF_W1L + off + 16) = make_uint4(l4, l5, 0u, 0u);
        ((float*)(base + OFF_B1))[tid] = b1[tid];
        ((float*)(base + OFF_B2))[tid] = b2[tid];
        ((float*)(base + OFF_WP))[tid] = Wp[tid];
    }
    if (tid == 0) *((float*)(base + OFF_BP)) = bp[0];
    __syncthreads();   // smem read-only from here; tile loop needs no syncs

    // ---- W1 B-fragments (persist across tiles) ----
    uint32_t B1h[8][2], B1l[8][2];
    {
        const int local = lane & 7, mat = lane >> 3;
        const int kc = mat & 1, ntoff = mat >> 1;
        #pragma unroll
        for (int p = 0; p < 4; p++) {
            const uint32_t roff = ((2 * p + ntoff) * 8 + local) * WSTR + kc * 16;
            uint32_t r[4];
            ldsm_x4(r, sb + OFF_W1H + roff);
            B1h[2 * p][0] = r[0]; B1h[2 * p][1] = r[1];
            B1h[2 * p + 1][0] = r[2]; B1h[2 * p + 1][1] = r[3];
            ldsm_x4(r, sb + OFF_W1L + roff);
            B1l[2 * p][0] = r[0]; B1l[2 * p][1] = r[1];
            B1l[2 * p + 1][0] = r[2]; B1l[2 * p + 1][1] = r[3];
        }
    }

    const int local = lane & 7, mat = lane >> 3;
    const int kc = mat & 1, ntoff = mat >> 1;
    const float bps = *((const float*)(base + OFF_BP));

    for (int t = 0; t < NTILES; t++) {
        const int nodebase = (blockIdx.x + t * GRID) * NPB + w * 32;

        // ---- layer-1 A fragments from global (K=16, cols 12-15 zero) ----
        uint32_t Ah1[2][4], Al1[2][4];
        #pragma unroll
        for (int mt = 0; mt < 2; mt++) {
            const int row0 = nodebase + mt * 16 + r4;
            const int row1 = row0 + 8;
            float2 v00 = make_float2(0.f, 0.f), v01 = v00, v10 = v00, v11 = v00;
            if (row0 < NN) {
                v00 = *(const float2*)(sf + (size_t)row0 * SF + 2 * q);
                if (q < 2) v01 = *(const float2*)(sf + (size_t)row0 * SF + 2 * q + 8);
            }
            if (row1 < NN) {
                v10 = *(const float2*)(sf + (size_t)row1 * SF + 2 * q);
                if (q < 2) v11 = *(const float2*)(sf + (size_t)row1 * SF + 2 * q + 8);
            }
            split2(v00.x, v00.y, Ah1[mt][0], Al1[mt][0]);
            split2(v10.x, v10.y, Ah1[mt][1], Al1[mt][1]);
            split2(v01.x, v01.y, Ah1[mt][2], Al1[mt][2]);
            split2(v11.x, v11.y, Ah1[mt][3], Al1[mt][3]);
        }

        // ---- layer-1 MMA ----
        float D1[2][8][4];
        #pragma unroll
        for (int mt = 0; mt < 2; mt++)
            #pragma unroll
            for (int n = 0; n < 8; n++) {
                #pragma unroll
                for (int c = 0; c < 4; c++) D1[mt][n][c] = 0.0f;
                mma_bf16(D1[mt][n], Ah1[mt], B1h[n]);
                mma_bf16(D1[mt][n], Al1[mt], B1h[n]);
                mma_bf16(D1[mt][n], Ah1[mt], B1l[n]);
            }

        // ---- epilogue-1: relu + b1; layer-2 A fragments (register chain) ----
        uint32_t A2h[2][4][4], A2l[2][4][4];
        {
            #pragma unroll
            for (int n = 0; n < 8; n++) {
                const float2 bv = *(const float2*)(base + OFF_B1 + (n * 8 + 2 * q) * 4);
                #pragma unroll
                for (int mt = 0; mt < 2; mt++) {
                    D1[mt][n][0] = fmaxf(D1[mt][n][0] + bv.x, 0.0f);
                    D1[mt][n][1] = fmaxf(D1[mt][n][1] + bv.y, 0.0f);
                    D1[mt][n][2] = fmaxf(D1[mt][n][2] + bv.x, 0.0f);
                    D1[mt][n][3] = fmaxf(D1[mt][n][3] + bv.y, 0.0f);
                }
            }
            #pragma unroll
            for (int mt = 0; mt < 2; mt++)
                #pragma unroll
                for (int kt = 0; kt < 4; kt++) {
                    split2(D1[mt][2 * kt][0],     D1[mt][2 * kt][1],     A2h[mt][kt][0], A2l[mt][kt][0]);
                    split2(D1[mt][2 * kt][2],     D1[mt][2 * kt][3],     A2h[mt][kt][1], A2l[mt][kt][1]);
                    split2(D1[mt][2 * kt + 1][0], D1[mt][2 * kt + 1][1], A2h[mt][kt][2], A2l[mt][kt][2]);
                    split2(D1[mt][2 * kt + 1][2], D1[mt][2 * kt + 1][3], A2h[mt][kt][3], A2l[mt][kt][3]);
                }
        }

        // ---- layer-2 MMA: D2 = A2h*B2h + A2l*B2h + A2h*B2l ----
        float D2[2][8][4];
        #pragma unroll
        for (int mt = 0; mt < 2; mt++)
            #pragma unroll
            for (int n = 0; n < 8; n++)
                #pragma unroll
                for (int c = 0; c < 4; c++) D2[mt][n][c] = 0.0f;

        #pragma unroll
        for (int kt = 0; kt < 4; kt++) {
            #pragma unroll
            for (int p = 0; p < 4; p++) {
                const uint32_t roff = ((2 * p + ntoff) * 8 + local) * BSTR + kt * 32 + kc * 16;
                uint32_t bh[4], bl[4];
                ldsm_x4(bh, sb + OFF_B2H + roff);
                ldsm_x4(bl, sb + OFF_B2L + roff);
                #pragma unroll
                for (int mt = 0; mt < 2; mt++) {
                    mma_bf16(D2[mt][2 * p],     A2h[mt][kt], &bh[0]);
                    mma_bf16(D2[mt][2 * p],     A2l[mt][kt], &bh[0]);
                    mma_bf16(D2[mt][2 * p],     A2h[mt][kt], &bl[0]);
                    mma_bf16(D2[mt][2 * p + 1], A2h[mt][kt], &bh[2]);
                    mma_bf16(D2[mt][2 * p + 1], A2l[mt][kt], &bh[2]);
                    mma_bf16(D2[mt][2 * p + 1], A2h[mt][kt], &bl[2]);
                }
            }
        }

        // ---- epilogue-2: relu + b2, dot with Wp, quad-reduce, store ----
        #pragma unroll
        for (int mt = 0; mt < 2; mt++) {
            float p0 = 0.0f, p1 = 0.0f;
            #pragma unroll
            for (int n = 0; n < 8; n++) {
                const float2 g  = *(const float2*)(base + OFF_B2 + (n * 8 + 2 * q) * 4);
                const float2 wv = *(const float2*)(base + OFF_WP + (n * 8 + 2 * q) * 4);
                p0 = fmaf(wv.x, fmaxf(D2[mt][n][0] + g.x, 0.0f), p0);
                p0 = fmaf(wv.y, fmaxf(D2[mt][n][1] + g.y, 0.0f), p0);
                p1 = fmaf(wv.x, fmaxf(D2[mt][n][2] + g.x, 0.0f), p1);
                p1 = fmaf(wv.y, fmaxf(D2[mt][n][3] + g.y, 0.0f), p1);
            }
            p0 += __shfl_xor_sync(0xffffffffu, p0, 1);
            p0 += __shfl_xor_sync(0xffffffffu, p0, 2);
            p1 += __shfl_xor_sync(0xffffffffu, p1, 1);
            p1 += __shfl_xor_sync(0xffffffffu, p1, 2);
            if (q == 0) {
                const int n0 = nodebase + mt * 16 + r4;
                if (n0 < NN)     out[n0]     = p0 + bps;
                if (n0 + 8 < NN) out[n0 + 8] = p1 + bps;
            }
        }
    }
}

extern "C" void kernel_launch(void* const* d_in, const int* in_sizes, int n_in,
                              void* d_out, int out_size)
{
    const float* sf = (const float*)d_in[2];
    const float* W1 = (const float*)d_in[9];
    const float* b1 = (const float*)d_in[10];
    const float* W2 = (const float*)d_in[11];
    const float* b2 = (const float*)d_in[12];
    const float* Wp = (const float*)d_in[13];
    const float* bp = (const float*)d_in[14];
    float* out = (float*)d_out;

    cudaFuncSetAttribute(fused_mlp_hmma3,
                         cudaFuncAttributeMaxDynamicSharedMemorySize, SMEM_DYN);
    fused_mlp_hmma3<<<GRID, TPB, SMEM_DYN>>>(sf, W1, b1, W2, b2, Wp, bp, out);
}

// round 9
// speedup vs baseline: 1.0597x; 1.0597x over previous
#include <cuda_runtime.h>
#include <cuda_bf16.h>
#include <cstdint>

// Live computation (GNN branch is dead code in the reference):
//   h1 = relu(sf @ Wfc1^T + bfc1)     [N,12] -> [N,64]   (HMMA, K padded to 16)
//   h2 = relu(h1 @ Wfc2^T + bfc2)     [N,64] -> [N,64]   (HMMA, A register-chained)
//   out = h2 @ Wp^T + bp              [N,64] -> [N,1]    (register epilogue)
//
// Round 9: latency-bound fix. M=16 per warp (8 warps/block, TPB=256) cuts
// per-thread registers to ~110 -> 2 CTAs/SM = 4 warps/SMSP. Layer-2 MMAs are
// term-major ordered: 8 independent accumulator chains, dependent HMMAs 8
// issues apart instead of back-to-back.

#define NN     100000
#define SF     12
#define FC     64
#define TPB    256
#define NPB    128
#define BSTR   144            // W2 smem row stride (bytes): 9x16B, conflict-free
#define WSTR   48             // W1 smem row stride (bytes): 3x16B, conflict-free

// ---- dynamic smem layout (byte offsets) ----
#define OFF_B2H  0            // 64 x 144
#define OFF_B2L  9216         // 64 x 144
#define OFF_W1H  18432        // 64 x 48
#define OFF_W1L  21504        // 64 x 48
#define OFF_B1   24576        // float[64]
#define OFF_B2   24832        // float[64]
#define OFF_WP   25088        // float[64]
#define OFF_BP   25344        // float
#define SMEM_DYN 25600

__device__ __forceinline__ uint32_t smem_u32(const void* p) {
    uint32_t a;
    asm("{ .reg .u64 t; cvta.to.shared.u64 t, %1; cvt.u32.u64 %0, t; }"
        : "=r"(a) : "l"(p));
    return a;
}
// pack: f0 -> low bf16, f1 -> high bf16
__device__ __forceinline__ uint32_t bf16x2_of(float f0, float f1) {
    uint32_t r;
    asm("cvt.rn.bf16x2.f32 %0, %1, %2;" : "=r"(r) : "f"(f1), "f"(f0));
    return r;
}
__device__ __forceinline__ void split2(float f0, float f1, uint32_t& h, uint32_t& l) {
    h = bf16x2_of(f0, f1);
    float g0 = __uint_as_float(h << 16);
    float g1 = __uint_as_float(h & 0xffff0000u);
    l = bf16x2_of(f0 - g0, f1 - g1);
}
__device__ __forceinline__ void ldsm_x4(uint32_t* r, uint32_t addr) {
    asm volatile("ldmatrix.sync.aligned.m8n8.x4.shared.b16 {%0,%1,%2,%3}, [%4];"
                 : "=r"(r[0]), "=r"(r[1]), "=r"(r[2]), "=r"(r[3]) : "r"(addr));
}
__device__ __forceinline__ void mma_bf16(float* d, const uint32_t* a, const uint32_t* b) {
    asm volatile(
        "mma.sync.aligned.m16n8k16.row.col.f32.bf16.bf16.f32 "
        "{%0,%1,%2,%3}, {%4,%5,%6,%7}, {%8,%9}, {%0,%1,%2,%3};"
        : "+f"(d[0]), "+f"(d[1]), "+f"(d[2]), "+f"(d[3])
        : "r"(a[0]), "r"(a[1]), "r"(a[2]), "r"(a[3]), "r"(b[0]), "r"(b[1]));
}

__global__ __launch_bounds__(TPB, 2)
void fused_mlp_hmma4(const float* __restrict__ sf,
                     const float* __restrict__ W1, const float* __restrict__ b1,
                     const float* __restrict__ W2, const float* __restrict__ b2,
                     const float* __restrict__ Wp, const float* __restrict__ bp,
                     float* __restrict__ out)
{
    extern __shared__ __align__(16) char base[];
    const uint32_t sb = smem_u32(base);

    const int tid  = threadIdx.x;
    const int lane = tid & 31;
    const int w    = tid >> 5;          // 0..7
    const int q    = lane & 3;
    const int r4   = lane >> 2;

    // ---- stage W2 -> B2h/B2l (rows = output j, 64 bf16 k-contig, stride 144) ----
    {
        const int row = tid >> 2, quarter = tid & 3;   // 16 floats per thread
        const float* src = W2 + row * FC + quarter * 16;
        #pragma unroll
        for (int g = 0; g < 2; g++) {
            float4 v0 = *(const float4*)(src + g * 8);
            float4 v1 = *(const float4*)(src + g * 8 + 4);
            uint32_t h0, l0, h1_, l1_, h2, l2, h3, l3;
            split2(v0.x, v0.y, h0, l0);
            split2(v0.z, v0.w, h1_, l1_);
            split2(v1.x, v1.y, h2, l2);
            split2(v1.z, v1.w, h3, l3);
            const int off = row * BSTR + quarter * 32 + g * 16;
            *(uint4*)(base + OFF_B2H + off) = make_uint4(h0, h1_, h2, h3);
            *(uint4*)(base + OFF_B2L + off) = make_uint4(l0, l1_, l2, l3);
        }
    }
    // ---- stage W1 -> W1h/W1l (12 bf16 + 4 zero pad per row, stride 48) ----
    if (tid < FC) {
        const float* src = W1 + tid * SF;
        float4 v0 = *(const float4*)(src);
        float4 v1 = *(const float4*)(src + 4);
        float4 v2 = *(const float4*)(src + 8);
        uint32_t h0, l0, h1_, l1_, h2, l2, h3, l3, h4, l4, h5, l5;
        split2(v0.x, v0.y, h0, l0);
        split2(v0.z, v0.w, h1_, l1_);
        split2(v1.x, v1.y, h2, l2);
        split2(v1.z, v1.w, h3, l3);
        split2(v2.x, v2.y, h4, l4);
        split2(v2.z, v2.w, h5, l5);
        const int off = tid * WSTR;
        *(uint4*)(base + OFF_W1H + off)      = make_uint4(h0, h1_, h2, h3);
        *(uint4*)(base + OFF_W1H + off + 16) = make_uint4(h4, h5, 0u, 0u);
        *(uint4*)(base + OFF_W1L + off)      = make_uint4(l0, l1_, l2, l3);
        *(uint4*)(base + OFF_W1L + off + 16) = make_uint4(l4, l5, 0u, 0u);
        ((float*)(base + OFF_B1))[tid] = b1[tid];
        ((float*)(base + OFF_B2))[tid] = b2[tid];
        ((float*)(base + OFF_WP))[tid] = Wp[tid];
    }
    if (tid == 0) *((float*)(base + OFF_BP)) = bp[0];

    // ---- layer-1 A fragments from global (M=16 rows, K=16, cols 12-15 zero) ----
    const int mbase = blockIdx.x * NPB + w * 16;
    uint32_t Ah1[4], Al1[4];
    {
        const int row0 = mbase + r4;
        const int row1 = row0 + 8;
        float2 v00 = make_float2(0.f, 0.f), v01 = v00, v10 = v00, v11 = v00;
        if (row0 < NN) {
            v00 = *(const float2*)(sf + (size_t)row0 * SF + 2 * q);
            if (q < 2) v01 = *(const float2*)(sf + (size_t)row0 * SF + 2 * q + 8);
        }
        if (row1 < NN) {
            v10 = *(const float2*)(sf + (size_t)row1 * SF + 2 * q);
            if (q < 2) v11 = *(const float2*)(sf + (size_t)row1 * SF + 2 * q + 8);
        }
        split2(v00.x, v00.y, Ah1[0], Al1[0]);
        split2(v10.x, v10.y, Ah1[1], Al1[1]);
        split2(v01.x, v01.y, Ah1[2], Al1[2]);
        split2(v11.x, v11.y, Ah1[3], Al1[3]);
    }
    __syncthreads();   // all smem staged

    const int local = lane & 7, mat = lane >> 3;
    const int kc = mat & 1, ntoff = mat >> 1;

    // ---- layer-1 MMA: D1[8][4], term-major (8 independent chains) ----
    float D1[8][4];
    {
        uint32_t B1h[8][2], B1l[8][2];
        #pragma unroll
        for (int p = 0; p < 4; p++) {
            const uint32_t roff = ((2 * p + ntoff) * 8 + local) * WSTR + kc * 16;
            uint32_t r[4];
            ldsm_x4(r, sb + OFF_W1H + roff);
            B1h[2 * p][0] = r[0]; B1h[2 * p][1] = r[1];
            B1h[2 * p + 1][0] = r[2]; B1h[2 * p + 1][1] = r[3];
            ldsm_x4(r, sb + OFF_W1L + roff);
            B1l[2 * p][0] = r[0]; B1l[2 * p][1] = r[1];
            B1l[2 * p + 1][0] = r[2]; B1l[2 * p + 1][1] = r[3];
        }
        #pragma unroll
        for (int n = 0; n < 8; n++) {
            #pragma unroll
            for (int c = 0; c < 4; c++) D1[n][c] = 0.0f;
        }
        #pragma unroll
        for (int n = 0; n < 8; n++) mma_bf16(D1[n], Ah1, B1h[n]);
        #pragma unroll
        for (int n = 0; n < 8; n++) mma_bf16(D1[n], Al1, B1h[n]);
        #pragma unroll
        for (int n = 0; n < 8; n++) mma_bf16(D1[n], Ah1, B1l[n]);
    }

    // ---- epilogue-1: relu + b1; layer-2 A fragments (register chain) ----
    // k-tile kt of layer-2 A == D1 n-tiles {2kt, 2kt+1}.
    uint32_t A2h[4][4], A2l[4][4];
    {
        #pragma unroll
        for (int n = 0; n < 8; n++) {
            const float2 bv = *(const float2*)(base + OFF_B1 + (n * 8 + 2 * q) * 4);
            D1[n][0] = fmaxf(D1[n][0] + bv.x, 0.0f);
            D1[n][1] = fmaxf(D1[n][1] + bv.y, 0.0f);
            D1[n][2] = fmaxf(D1[n][2] + bv.x, 0.0f);
            D1[n][3] = fmaxf(D1[n][3] + bv.y, 0.0f);
        }
        #pragma unroll
        for (int kt = 0; kt < 4; kt++) {
            split2(D1[2 * kt][0],     D1[2 * kt][1],     A2h[kt][0], A2l[kt][0]);
            split2(D1[2 * kt][2],     D1[2 * kt][3],     A2h[kt][1], A2l[kt][1]);
            split2(D1[2 * kt + 1][0], D1[2 * kt + 1][1], A2h[kt][2], A2l[kt][2]);
            split2(D1[2 * kt + 1][2], D1[2 * kt + 1][3], A2h[kt][3], A2l[kt][3]);
        }
    }

    // ---- layer-2 MMA: D2 = A2h*B2h + A2l*B2h + A2h*B2l, term-major per kt ----
    float D2[8][4];
    #pragma unroll
    for (int n = 0; n < 8; n++)
        #pragma unroll
        for (int c = 0; c < 4; c++) D2[n][c] = 0.0f;

    #pragma unroll
    for (int kt = 0; kt < 4; kt++) {
        uint32_t bh[4][4], bl[4][4];
        #pragma unroll
        for (int p = 0; p < 4; p++) {
            const uint32_t roff = ((2 * p + ntoff) * 8 + local) * BSTR + kt * 32 + kc * 16;
            ldsm_x4(bh[p], sb + OFF_B2H + roff);
            ldsm_x4(bl[p], sb + OFF_B2L + roff);
        }
        // term 1: Ah*Bh -> 8 distinct accumulators
        #pragma unroll
        for (int p = 0; p < 4; p++) {
            mma_bf16(D2[2 * p],     A2h[kt], &bh[p][0]);
            mma_bf16(D2[2 * p + 1], A2h[kt], &bh[p][2]);
        }
        // term 2: Al*Bh
        #pragma unroll
        for (int p = 0; p < 4; p++) {
            mma_bf16(D2[2 * p],     A2l[kt], &bh[p][0]);
            mma_bf16(D2[2 * p + 1], A2l[kt], &bh[p][2]);
        }
        // term 3: Ah*Bl
        #pragma unroll
        for (int p = 0; p < 4; p++) {
            mma_bf16(D2[2 * p],     A2h[kt], &bl[p][0]);
            mma_bf16(D2[2 * p + 1], A2h[kt], &bl[p][2]);
        }
    }

    // ---- epilogue-2: relu + b2, dot with Wp, quad-reduce, store ----
    {
        const float bps = *((const float*)(base + OFF_BP));
        float p0 = 0.0f, p1 = 0.0f;
        #pragma unroll
        for (int n = 0; n < 8; n++) {
            const float2 g  = *(const float2*)(base + OFF_B2 + (n * 8 + 2 * q) * 4);
            const float2 wv = *(const float2*)(base + OFF_WP + (n * 8 + 2 * q) * 4);
            p0 = fmaf(wv.x, fmaxf(D2[n][0] + g.x, 0.0f), p0);
            p0 = fmaf(wv.y, fmaxf(D2[n][1] + g.y, 0.0f), p0);
            p1 = fmaf(wv.x, fmaxf(D2[n][2] + g.x, 0.0f), p1);
            p1 = fmaf(wv.y, fmaxf(D2[n][3] + g.y, 0.0f), p1);
        }
        p0 += __shfl_xor_sync(0xffffffffu, p0, 1);
        p0 += __shfl_xor_sync(0xffffffffu, p0, 2);
        p1 += __shfl_xor_sync(0xffffffffu, p1, 1);
        p1 += __shfl_xor_sync(0xffffffffu, p1, 2);
        if (q == 0) {
            const int n0 = mbase + r4;
            if (n0 < NN)     out[n0]     = p0 + bps;
            if (n0 + 8 < NN) out[n0 + 8] = p1 + bps;
        }
    }
}

extern "C" void kernel_launch(void* const* d_in, const int* in_sizes, int n_in,
                              void* d_out, int out_size)
{
    const float* sf = (const float*)d_in[2];
    const float* W1 = (const float*)d_in[9];
    const float* b1 = (const float*)d_in[10];
    const float* W2 = (const float*)d_in[11];
    const float* b2 = (const float*)d_in[12];
    const float* Wp = (const float*)d_in[13];
    const float* bp = (const float*)d_in[14];
    float* out = (float*)d_out;

    cudaFuncSetAttribute(fused_mlp_hmma4,
                         cudaFuncAttributeMaxDynamicSharedMemorySize, SMEM_DYN);
    const int grid = (NN + NPB - 1) / NPB;   // 782
    fused_mlp_hmma4<<<grid, TPB, SMEM_DYN>>>(sf, W1, b1, W2, b2, Wp, bp, out);
}